// round 1
// baseline (speedup 1.0000x reference)
#include <cuda_runtime.h>
#include <math.h>

// Problem constants
#define NN    65536
#define EE    1048576
#define TPAST 20
#define TFUT  40
#define HK    48
#define H3    144
#define D3    432

// Capacities (edges are uniform random; col==0 count ~Poisson(16))
#define CAP1  4096    // edges into node 0 / S1 slots
#define CAPE  65536   // edges into S1 nodes
#define MAX2  70000   // S2 node slots

// ---------------- device scratch (no allocations allowed) ----------------
__device__ float g_deg[NN];
__device__ int   g_slot1[NN];
__device__ int   g_slot2[NN];
__device__ int   g_s1rows[CAP1];
__device__ float g_s1w[CAP1];
__device__ int   g_s1nodes[CAP1];
__device__ int   g_s2erow[CAPE];
__device__ int   g_s2ecol[CAPE];
__device__ float g_s2ew[CAPE];
__device__ int   g_s2nodes[MAX2];
__device__ float g_xw1[MAX2 * HK];     // state_past @ gcn1_w.T per S2 slot
__device__ float g_x1acc[CAP1 * HK];
__device__ float g_x1[CAP1 * HK];      // relu'd layer-1 at S1 slots
__device__ float g_interact[HK];
__device__ float g_target[HK];
__device__ float g_futv[HK];
__device__ __align__(16) float g_whhT[H3 * D3];  // transposed dec_Whh [144][432]
__device__ __align__(16) float g_wihT[H3 * D3];  // transposed dec_Wih [144][432]
__device__ int g_s1cnt, g_n1, g_s2ecnt, g_n2;

__device__ __forceinline__ float sigmoidf(float x) { return 1.0f / (1.0f + expf(-x)); }

// ---------------- init / pack ----------------
__global__ void k_init() {
    int stride = gridDim.x * blockDim.x;
    for (int i = blockIdx.x * blockDim.x + threadIdx.x; i < CAP1 * HK; i += stride) {
        if (i < NN) { g_deg[i] = 1.0f; g_slot1[i] = -1; g_slot2[i] = -1; }
        g_x1acc[i] = 0.f;
    }
    if (blockIdx.x == 0 && threadIdx.x == 0) { g_s1cnt = 0; g_n1 = 0; g_s2ecnt = 0; g_n2 = 0; }
}

__global__ void k_pack(const float* __restrict__ Whh, const float* __restrict__ Wih) {
    int stride = gridDim.x * blockDim.x;
    for (int l = blockIdx.x * blockDim.x + threadIdx.x; l < H3 * D3; l += stride) {
        int j = l / D3, r = l - j * D3;
        g_whhT[l] = Whh[r * H3 + j];
        g_wihT[l] = Wih[r * H3 + j];
    }
}

// ---------------- edge passes ----------------
__global__ void k_passA(const int* __restrict__ ei, const float* __restrict__ ew) {
    int stride = gridDim.x * blockDim.x;
    for (int e = blockIdx.x * blockDim.x + threadIdx.x; e < EE; e += stride) {
        int col = ei[EE + e];
        float w = ew[e];
        atomicAdd(&g_deg[col], w);
        if (col == 0) {
            int pos = atomicAdd(&g_s1cnt, 1);
            if (pos < CAP1) { g_s1rows[pos] = ei[e]; g_s1w[pos] = w; }
        }
    }
}

__global__ void k_s1nodes() {
    int n = min(g_s1cnt, CAP1);
    for (int i = threadIdx.x; i <= n; i += blockDim.x) {
        int v = (i == n) ? 0 : g_s1rows[i];
        if (atomicCAS(&g_slot1[v], -1, -2) == -1) {
            int s = atomicAdd(&g_n1, 1);
            if (s < CAP1) g_s1nodes[s] = v;
            g_slot1[v] = s;
        }
        if (atomicCAS(&g_slot2[v], -1, -2) == -1) {
            int s = atomicAdd(&g_n2, 1);
            if (s < MAX2) g_s2nodes[s] = v;
            g_slot2[v] = s;
        }
    }
}

__global__ void k_passB(const int* __restrict__ ei, const float* __restrict__ ew) {
    int stride = gridDim.x * blockDim.x;
    for (int e = blockIdx.x * blockDim.x + threadIdx.x; e < EE; e += stride) {
        int col = ei[EE + e];
        if (g_slot1[col] >= 0) {
            int row = ei[e];
            int pos = atomicAdd(&g_s2ecnt, 1);
            if (pos < CAPE) { g_s2erow[pos] = row; g_s2ecol[pos] = col; g_s2ew[pos] = ew[e]; }
            if (atomicCAS(&g_slot2[row], -1, -2) == -1) {
                int s = atomicAdd(&g_n2, 1);
                if (s < MAX2) g_s2nodes[s] = row;
                g_slot2[row] = s;
            }
        }
    }
}

// ---------------- conv1d+GRU sequence (shared-memory block routine) ----------------
// weights in registers (row per thread), activations in shared
__device__ void gru_seq(const float* __restrict__ xin, int T,
                        const float* __restrict__ cw, const float* __restrict__ cb,
                        const float* __restrict__ Wih, const float* __restrict__ Whh,
                        const float* __restrict__ bih, const float* __restrict__ bhh,
                        float* xs, float* xe, float* ga, float* gb, float* h) {
    int tid = threadIdx.x;
    for (int i = tid; i < 2 * T; i += blockDim.x) xs[i] = xin[i];
    if (tid < HK) h[tid] = 0.f;
    __syncthreads();
    // conv1d (pad 1) + relu
    for (int idx = tid; idx < T * HK; idx += blockDim.x) {
        int t = idx / HK, k = idx - t * HK;
        float acc = cb[k];
        #pragma unroll
        for (int j = 0; j < 3; j++) {
            int tt = t + j - 1;
            if (tt >= 0 && tt < T)
                acc += xs[tt * 2 + 0] * cw[(k * 2 + 0) * 3 + j]
                     + xs[tt * 2 + 1] * cw[(k * 2 + 1) * 3 + j];
        }
        xe[idx] = fmaxf(acc, 0.f);
    }
    float wi[HK], wh[HK];
    float bi = 0.f, bh = 0.f;
    if (tid < H3) {
        #pragma unroll
        for (int j = 0; j < HK; j++) { wi[j] = Wih[tid * HK + j]; wh[j] = Whh[tid * HK + j]; }
        bi = bih[tid]; bh = bhh[tid];
    }
    __syncthreads();
    for (int t = 0; t < T; t++) {
        if (tid < H3) {
            float a = bi, b = bh;
            const float* xt = &xe[t * HK];
            #pragma unroll
            for (int j = 0; j < HK; j++) { a += wi[j] * xt[j]; b += wh[j] * h[j]; }
            ga[tid] = a; gb[tid] = b;
        }
        __syncthreads();
        float hn = 0.f;
        if (tid < HK) {
            float r = sigmoidf(ga[tid] + gb[tid]);
            float z = sigmoidf(ga[HK + tid] + gb[HK + tid]);
            float n = tanhf(ga[2 * HK + tid] + r * gb[2 * HK + tid]);
            hn = (1.f - z) * n + z * h[tid];
        }
        __syncthreads();
        if (tid < HK) h[tid] = hn;
        __syncthreads();
    }
}

// GRU over the pruned S2 node set; also produces xw1 = state @ gcn1_w.T
__global__ __launch_bounds__(160) void k_gru_nodes(
    const float* __restrict__ x,
    const float* __restrict__ cw, const float* __restrict__ cb,
    const float* __restrict__ Wih, const float* __restrict__ Whh,
    const float* __restrict__ bih, const float* __restrict__ bhh,
    const float* __restrict__ g1w) {
    __shared__ float xs[2 * TPAST], xe[TPAST * HK], ga[H3], gb[H3], h[HK];
    int n2 = min(g_n2, MAX2);
    for (int i = blockIdx.x; i < n2; i += gridDim.x) {
        int node = g_s2nodes[i];
        gru_seq(x + (size_t)node * (2 * TPAST), TPAST, cw, cb, Wih, Whh, bih, bhh,
                xs, xe, ga, gb, h);
        if (threadIdx.x < HK) {
            float acc = 0.f;
            #pragma unroll
            for (int j = 0; j < HK; j++) acc += h[j] * g1w[threadIdx.x * HK + j];
            g_xw1[i * HK + threadIdx.x] = acc;
        }
        __syncthreads();
    }
}

// target_past (past, 20 steps) and state_fut (future, 40 steps)
__global__ __launch_bounds__(160) void k_gru_single(
    const float* __restrict__ past, const float* __restrict__ future,
    const float* __restrict__ cpw, const float* __restrict__ cpb,
    const float* __restrict__ cfw, const float* __restrict__ cfb,
    const float* __restrict__ pWih, const float* __restrict__ pWhh,
    const float* __restrict__ pbih, const float* __restrict__ pbhh,
    const float* __restrict__ fWih, const float* __restrict__ fWhh,
    const float* __restrict__ fbih, const float* __restrict__ fbhh) {
    __shared__ float xs[2 * TFUT], xe[TFUT * HK], ga[H3], gb[H3], h[HK];
    if (blockIdx.x == 0) {
        gru_seq(past, TPAST, cpw, cpb, pWih, pWhh, pbih, pbhh, xs, xe, ga, gb, h);
        if (threadIdx.x < HK) g_target[threadIdx.x] = h[threadIdx.x];
    } else {
        gru_seq(future, TFUT, cfw, cfb, fWih, fWhh, fbih, fbhh, xs, xe, ga, gb, h);
        if (threadIdx.x < HK) g_futv[threadIdx.x] = h[threadIdx.x];
    }
}

// ---------------- GCN layers on the pruned cone ----------------
__global__ void k_layer1() {
    int ne = min(g_s2ecnt, CAPE);
    int total = ne * HK;
    int stride = gridDim.x * blockDim.x;
    for (int idx = blockIdx.x * blockDim.x + threadIdx.x; idx < total; idx += stride) {
        int e = idx / HK, k = idx - e * HK;
        int row = g_s2erow[e], col = g_s2ecol[e];
        float norm = rsqrtf(g_deg[row]) * g_s2ew[e] * rsqrtf(g_deg[col]);
        int s2 = g_slot2[row];
        int s1 = g_slot1[col];
        if (s2 >= 0 && s2 < MAX2 && s1 >= 0 && s1 < CAP1)
            atomicAdd(&g_x1acc[s1 * HK + k], g_xw1[s2 * HK + k] * norm);
    }
}

__global__ void k_layer1fin(const float* __restrict__ b1) {
    int n1 = min(g_n1, CAP1);
    int stride = gridDim.x * blockDim.x;
    for (int idx = blockIdx.x * blockDim.x + threadIdx.x; idx < n1 * HK; idx += stride) {
        int s = idx / HK, k = idx - s * HK;
        int v = g_s1nodes[s];
        float self = g_xw1[g_slot2[v] * HK + k] / g_deg[v];
        g_x1[idx] = fmaxf(g_x1acc[idx] + self + b1[k], 0.f);
    }
}

__global__ void k_layer2(const float* __restrict__ g2w, const float* __restrict__ g2b) {
    __shared__ float coef[1024];
    __shared__ float xagg[HK];
    int tid = threadIdx.x;
    int n1 = min(g_n1, 1024);
    int ncnt = min(g_s1cnt, CAP1);
    for (int i = tid; i < n1; i += blockDim.x) coef[i] = 0.f;
    __syncthreads();
    float d0 = rsqrtf(g_deg[0]);
    for (int i = tid; i < ncnt; i += blockDim.x) {
        int row = g_s1rows[i];
        float nrm = rsqrtf(g_deg[row]) * g_s1w[i] * d0;
        int s = g_slot1[row];
        if (s >= 0 && s < n1) atomicAdd(&coef[s], nrm);
    }
    __syncthreads();
    if (tid == 0) coef[g_slot1[0]] += 1.0f / g_deg[0];
    __syncthreads();
    if (tid < HK) {
        float a = 0.f;
        for (int s = 0; s < n1; s++) a += coef[s] * g_x1[s * HK + tid];
        xagg[tid] = a;
    }
    __syncthreads();
    if (tid < HK) {
        float a = g2b[tid];
        #pragma unroll
        for (int j = 0; j < HK; j++) a += xagg[j] * g2w[tid * HK + j];
        g_interact[tid] = a;
    }
}

// ---------------- decoder: 40-step GRU(hidden=144) + fc, coalesced matvec ----------------
__global__ __launch_bounds__(448) void k_decoder(
    const float* __restrict__ past,
    const float* __restrict__ dbih, const float* __restrict__ dbhh,
    const float* __restrict__ fcw, const float* __restrict__ fcb,
    float* __restrict__ out) {
    __shared__ float sc[H3], h[H3], ga0[D3], gbs[D3], bihs[D3], bhhs[D3];
    __shared__ float4 part[D3];
    __shared__ float pres[2];
    int tid = threadIdx.x;
    if (tid < HK) { sc[tid] = g_interact[tid]; sc[HK + tid] = g_target[tid]; sc[2 * HK + tid] = g_futv[tid]; }
    if (tid < H3) h[tid] = 0.f;
    if (tid < D3) { bihs[tid] = dbih[tid]; bhhs[tid] = dbhh[tid]; }
    if (tid < 2) pres[tid] = past[(TPAST - 1) * 2 + tid];
    __syncthreads();
    int q = tid >> 2, p = tid & 3;
    const float4* WHP = reinterpret_cast<const float4*>(g_whhT);
    const float4* WIP = reinterpret_cast<const float4*>(g_wihT);
    // gi0 = dec_Wih @ state_conc + bih (only step 0; later steps input is zero)
    if (tid < D3) {
        float4 acc = make_float4(0.f, 0.f, 0.f, 0.f);
        int j0 = p * 36;
        #pragma unroll 4
        for (int j = j0; j < j0 + 36; j++) {
            float4 wv = WIP[j * 108 + q];
            float s = sc[j];
            acc.x += wv.x * s; acc.y += wv.y * s; acc.z += wv.z * s; acc.w += wv.w * s;
        }
        part[tid] = acc;
    }
    __syncthreads();
    if (tid < 108) {
        float4 a = part[4 * tid], b = part[4 * tid + 1], c = part[4 * tid + 2], d = part[4 * tid + 3];
        ga0[4 * tid + 0] = a.x + b.x + c.x + d.x + bihs[4 * tid + 0];
        ga0[4 * tid + 1] = a.y + b.y + c.y + d.y + bihs[4 * tid + 1];
        ga0[4 * tid + 2] = a.z + b.z + c.z + d.z + bihs[4 * tid + 2];
        ga0[4 * tid + 3] = a.w + b.w + c.w + d.w + bihs[4 * tid + 3];
    }
    __syncthreads();
    for (int i = 0; i < TFUT; i++) {
        if (tid < D3) {
            float4 acc = make_float4(0.f, 0.f, 0.f, 0.f);
            int j0 = p * 36;
            #pragma unroll 4
            for (int j = j0; j < j0 + 36; j++) {
                float4 wv = WHP[j * 108 + q];
                float hv = h[j];
                acc.x += wv.x * hv; acc.y += wv.y * hv; acc.z += wv.z * hv; acc.w += wv.w * hv;
            }
            part[tid] = acc;
        }
        __syncthreads();
        if (tid < 108) {
            float4 a = part[4 * tid], b = part[4 * tid + 1], c = part[4 * tid + 2], d = part[4 * tid + 3];
            gbs[4 * tid + 0] = a.x + b.x + c.x + d.x + bhhs[4 * tid + 0];
            gbs[4 * tid + 1] = a.y + b.y + c.y + d.y + bhhs[4 * tid + 1];
            gbs[4 * tid + 2] = a.z + b.z + c.z + d.z + bhhs[4 * tid + 2];
            gbs[4 * tid + 3] = a.w + b.w + c.w + d.w + bhhs[4 * tid + 3];
        }
        __syncthreads();
        float hn = 0.f;
        if (tid < H3) {
            float gar = (i == 0) ? ga0[tid]          : bihs[tid];
            float gaz = (i == 0) ? ga0[H3 + tid]     : bihs[H3 + tid];
            float gan = (i == 0) ? ga0[2 * H3 + tid] : bihs[2 * H3 + tid];
            float r = sigmoidf(gar + gbs[tid]);
            float z = sigmoidf(gaz + gbs[H3 + tid]);
            float n = tanhf(gan + r * gbs[2 * H3 + tid]);
            hn = (1.f - z) * n + z * h[tid];
        }
        __syncthreads();
        if (tid < H3) h[tid] = hn;
        __syncthreads();
        if (tid < 64) {
            int d = tid >> 5, lane = tid & 31;
            float a = 0.f;
            for (int j = lane; j < H3; j += 32) a += h[j] * fcw[d * H3 + j];
            #pragma unroll
            for (int o = 16; o; o >>= 1) a += __shfl_down_sync(0xffffffffu, a, o);
            if (lane == 0) { pres[d] += a + fcb[d]; out[i * 2 + d] = pres[d]; }
        }
        __syncthreads();
    }
}

// ---------------- launch ----------------
extern "C" void kernel_launch(void* const* d_in, const int* in_sizes, int n_in,
                              void* d_out, int out_size) {
    (void)in_sizes; (void)n_in; (void)out_size;
    const float* past   = (const float*)d_in[0];
    const float* future = (const float*)d_in[1];
    const float* x      = (const float*)d_in[2];
    const int*   ei     = (const int*)  d_in[3];
    const float* ew     = (const float*)d_in[4];
    const float* cpw  = (const float*)d_in[5];
    const float* cpb  = (const float*)d_in[6];
    const float* cfw  = (const float*)d_in[7];
    const float* cfb  = (const float*)d_in[8];
    const float* pWih = (const float*)d_in[9];
    const float* pWhh = (const float*)d_in[10];
    const float* pbih = (const float*)d_in[11];
    const float* pbhh = (const float*)d_in[12];
    const float* fWih = (const float*)d_in[13];
    const float* fWhh = (const float*)d_in[14];
    const float* fbih = (const float*)d_in[15];
    const float* fbhh = (const float*)d_in[16];
    const float* dWih = (const float*)d_in[17];
    const float* dWhh = (const float*)d_in[18];
    const float* dbih = (const float*)d_in[19];
    const float* dbhh = (const float*)d_in[20];
    const float* fcw  = (const float*)d_in[21];
    const float* fcb  = (const float*)d_in[22];
    const float* g1w  = (const float*)d_in[23];
    const float* g1b  = (const float*)d_in[24];
    const float* g2w  = (const float*)d_in[25];
    const float* g2b  = (const float*)d_in[26];
    float* out = (float*)d_out;

    k_init<<<512, 256>>>();
    k_pack<<<128, 256>>>(dWhh, dWih);
    k_gru_single<<<2, 160>>>(past, future, cpw, cpb, cfw, cfb,
                             pWih, pWhh, pbih, pbhh, fWih, fWhh, fbih, fbhh);
    k_passA<<<512, 256>>>(ei, ew);
    k_s1nodes<<<1, 256>>>();
    k_passB<<<512, 256>>>(ei, ew);
    k_gru_nodes<<<1024, 160>>>(x, cpw, cpb, pWih, pWhh, pbih, pbhh, g1w);
    k_layer1<<<64, 256>>>();
    k_layer1fin<<<8, 256>>>(g1b);
    k_layer2<<<1, 256>>>(g2w, g2b);
    k_decoder<<<1, 448>>>(past, dbih, dbhh, fcw, fcb, out);
}

// round 3
// speedup vs baseline: 2.4269x; 2.4269x over previous
#include <cuda_runtime.h>
#include <math.h>

// Problem constants
#define NN    65536
#define EE    1048576
#define TPAST 20
#define TFUT  40
#define HK    48
#define H3    144
#define D3    432

// Capacities (edges uniform random; in-degree of node 0 ~ Poisson(16))
#define CAP1  4096
#define CAPE  65536
#define MAX2  70000

// ---------------- device scratch ----------------
__device__ float g_deg[NN];
__device__ int   g_slot1[NN];
__device__ int   g_slot2[NN];
__device__ int   g_s1rows[CAP1];
__device__ float g_s1w[CAP1];
__device__ int   g_s1nodes[CAP1];
__device__ int   g_s2erow[CAPE];
__device__ int   g_s2ecol[CAPE];
__device__ float g_s2ew[CAPE];
__device__ int   g_s2nodes[MAX2];
__device__ float g_xw1[MAX2 * HK];
__device__ float g_x1acc[CAP1 * HK];
__device__ float g_x1[CAP1 * HK];
__device__ float g_interact[HK];
__device__ float g_target[HK];
__device__ float g_futv[HK];
// decoder Whh re-laid-out for per-thread register slices: [((ct*3+p)*48+j)*H3 + o]
__device__ float g_wdecR[3 * 3 * 48 * H3];
// dec_Wih (432x144) transposed -> g_wihT[c*D3 + r] = Wih[r*H3 + c]
__device__ float g_wihT[H3 * D3];
__device__ int g_s1cnt, g_n1, g_s2ecnt, g_n2;

__device__ __forceinline__ float sigmoidf(float x) { return 1.0f / (1.0f + expf(-x)); }

// ---------------- prep: init scratch + repack decoder weights ----------------
__global__ void k_prep(const float* __restrict__ Whh, const float* __restrict__ Wih) {
    int stride = gridDim.x * blockDim.x;
    int t0 = blockIdx.x * blockDim.x + threadIdx.x;
    for (int i = t0; i < NN; i += stride) { g_deg[i] = 1.0f; g_slot1[i] = -1; g_slot2[i] = -1; }
    for (int i = t0; i < CAP1 * HK; i += stride) g_x1acc[i] = 0.f;
    // dec_Wih: shape (432, 144). Transpose to [col][row].
    for (int l = t0; l < D3 * H3; l += stride) {
        int r = l / H3, c = l - r * H3;
        g_wihT[c * D3 + r] = Wih[l];
    }
    // dec_Whh: shape (432, 144). Register-slice layout.
    for (int l = t0; l < 3 * 3 * 48 * H3; l += stride) {
        int o = l % H3;
        int j = (l / H3) % 48;
        int p = (l / (H3 * 48)) % 3;
        int ct = l / (H3 * 48 * 3);
        g_wdecR[l] = Whh[(ct * H3 + o) * H3 + (p * 48 + j)];
    }
    if (t0 == 0) { g_s1cnt = 0; g_n1 = 0; g_s2ecnt = 0; g_n2 = 0; }
}

// ---------------- edge passes (vectorized 4 edges/thread) ----------------
__global__ void k_passA(const int* __restrict__ ei, const float* __restrict__ ew) {
    int e4 = blockIdx.x * blockDim.x + threadIdx.x;
    if (e4 * 4 >= EE) return;
    int4 c = reinterpret_cast<const int4*>(ei + EE)[e4];
    float4 w = reinterpret_cast<const float4*>(ew)[e4];
    atomicAdd(&g_deg[c.x], w.x);
    atomicAdd(&g_deg[c.y], w.y);
    atomicAdd(&g_deg[c.z], w.z);
    atomicAdd(&g_deg[c.w], w.w);
    if (c.x == 0 || c.y == 0 || c.z == 0 || c.w == 0) {
        int4 r = reinterpret_cast<const int4*>(ei)[e4];
        if (c.x == 0) { int pos = atomicAdd(&g_s1cnt, 1); if (pos < CAP1) { g_s1rows[pos] = r.x; g_s1w[pos] = w.x; } }
        if (c.y == 0) { int pos = atomicAdd(&g_s1cnt, 1); if (pos < CAP1) { g_s1rows[pos] = r.y; g_s1w[pos] = w.y; } }
        if (c.z == 0) { int pos = atomicAdd(&g_s1cnt, 1); if (pos < CAP1) { g_s1rows[pos] = r.z; g_s1w[pos] = w.z; } }
        if (c.w == 0) { int pos = atomicAdd(&g_s1cnt, 1); if (pos < CAP1) { g_s1rows[pos] = r.w; g_s1w[pos] = w.w; } }
    }
}

__global__ void k_s1nodes() {
    int n = min(g_s1cnt, CAP1);
    for (int i = threadIdx.x; i <= n; i += blockDim.x) {
        int v = (i == n) ? 0 : g_s1rows[i];
        if (atomicCAS(&g_slot1[v], -1, -2) == -1) {
            int s = atomicAdd(&g_n1, 1);
            if (s < CAP1) g_s1nodes[s] = v;
            g_slot1[v] = s;
        }
        if (atomicCAS(&g_slot2[v], -1, -2) == -1) {
            int s = atomicAdd(&g_n2, 1);
            if (s < MAX2) g_s2nodes[s] = v;
            g_slot2[v] = s;
        }
    }
}

__device__ __forceinline__ void passB_one(int col, int row, float w) {
    if (g_slot1[col] >= 0) {
        int pos = atomicAdd(&g_s2ecnt, 1);
        if (pos < CAPE) { g_s2erow[pos] = row; g_s2ecol[pos] = col; g_s2ew[pos] = w; }
        if (atomicCAS(&g_slot2[row], -1, -2) == -1) {
            int s = atomicAdd(&g_n2, 1);
            if (s < MAX2) g_s2nodes[s] = row;
            g_slot2[row] = s;
        }
    }
}

__global__ void k_passB(const int* __restrict__ ei, const float* __restrict__ ew) {
    int e4 = blockIdx.x * blockDim.x + threadIdx.x;
    if (e4 * 4 >= EE) return;
    int4 c = reinterpret_cast<const int4*>(ei + EE)[e4];
    int4 r = reinterpret_cast<const int4*>(ei)[e4];
    float4 w = reinterpret_cast<const float4*>(ew)[e4];
    passB_one(c.x, r.x, w.x);
    passB_one(c.y, r.y, w.y);
    passB_one(c.z, r.z, w.z);
    passB_one(c.w, r.w, w.w);
}

// ---------------- conv1d+GRU sequence (per-block) ----------------
__device__ void gru_seq(const float* __restrict__ xin, int T,
                        const float* __restrict__ cw, const float* __restrict__ cb,
                        const float* __restrict__ Wih, const float* __restrict__ Whh,
                        const float* __restrict__ bih, const float* __restrict__ bhh,
                        float* xs, float* xe, float* ga, float* gb, float* h) {
    int tid = threadIdx.x;
    for (int i = tid; i < 2 * T; i += blockDim.x) xs[i] = xin[i];
    if (tid < HK) h[tid] = 0.f;
    __syncthreads();
    for (int idx = tid; idx < T * HK; idx += blockDim.x) {
        int t = idx / HK, k = idx - t * HK;
        float acc = cb[k];
        #pragma unroll
        for (int j = 0; j < 3; j++) {
            int tt = t + j - 1;
            if (tt >= 0 && tt < T)
                acc += xs[tt * 2 + 0] * cw[(k * 2 + 0) * 3 + j]
                     + xs[tt * 2 + 1] * cw[(k * 2 + 1) * 3 + j];
        }
        xe[idx] = fmaxf(acc, 0.f);
    }
    float wi[HK], wh[HK];
    float bi = 0.f, bh = 0.f;
    if (tid < H3) {
        #pragma unroll
        for (int j = 0; j < HK; j++) { wi[j] = Wih[tid * HK + j]; wh[j] = Whh[tid * HK + j]; }
        bi = bih[tid]; bh = bhh[tid];
    }
    __syncthreads();
    for (int t = 0; t < T; t++) {
        if (tid < H3) {
            float a0 = bi, a1 = 0.f, b0 = bh, b1 = 0.f;
            const float* xt = &xe[t * HK];
            #pragma unroll
            for (int j = 0; j < HK; j += 2) {
                a0 += wi[j] * xt[j];     a1 += wi[j + 1] * xt[j + 1];
                b0 += wh[j] * h[j];      b1 += wh[j + 1] * h[j + 1];
            }
            ga[tid] = a0 + a1; gb[tid] = b0 + b1;
        }
        __syncthreads();
        float hn = 0.f;
        if (tid < HK) {
            float r = sigmoidf(ga[tid] + gb[tid]);
            float z = sigmoidf(ga[HK + tid] + gb[HK + tid]);
            float n = tanhf(ga[2 * HK + tid] + r * gb[2 * HK + tid]);
            hn = (1.f - z) * n + z * h[tid];
        }
        __syncthreads();
        if (tid < HK) h[tid] = hn;
        __syncthreads();
    }
}

// blocks 0,1: target_past / state_fut; blocks 2+: pruned node set
__global__ __launch_bounds__(160) void k_gru_all(
    const float* __restrict__ x,
    const float* __restrict__ past, const float* __restrict__ future,
    const float* __restrict__ cpw, const float* __restrict__ cpb,
    const float* __restrict__ cfw, const float* __restrict__ cfb,
    const float* __restrict__ pWih, const float* __restrict__ pWhh,
    const float* __restrict__ pbih, const float* __restrict__ pbhh,
    const float* __restrict__ fWih, const float* __restrict__ fWhh,
    const float* __restrict__ fbih, const float* __restrict__ fbhh,
    const float* __restrict__ g1w) {
    __shared__ float xs[2 * TFUT], xe[TFUT * HK], ga[H3], gb[H3], h[HK];
    if (blockIdx.x == 0) {
        gru_seq(past, TPAST, cpw, cpb, pWih, pWhh, pbih, pbhh, xs, xe, ga, gb, h);
        if (threadIdx.x < HK) g_target[threadIdx.x] = h[threadIdx.x];
        return;
    }
    if (blockIdx.x == 1) {
        gru_seq(future, TFUT, cfw, cfb, fWih, fWhh, fbih, fbhh, xs, xe, ga, gb, h);
        if (threadIdx.x < HK) g_futv[threadIdx.x] = h[threadIdx.x];
        return;
    }
    int n2 = min(g_n2, MAX2);
    for (int i = blockIdx.x - 2; i < n2; i += gridDim.x - 2) {
        int node = g_s2nodes[i];
        gru_seq(x + (size_t)node * (2 * TPAST), TPAST, cpw, cpb, pWih, pWhh, pbih, pbhh,
                xs, xe, ga, gb, h);
        if (threadIdx.x < HK) {
            float acc = 0.f;
            #pragma unroll
            for (int j = 0; j < HK; j++) acc += h[j] * g1w[threadIdx.x * HK + j];
            g_xw1[i * HK + threadIdx.x] = acc;
        }
        __syncthreads();
    }
}

// ---------------- GCN cone ----------------
__global__ void k_layer1() {
    int ne = min(g_s2ecnt, CAPE);
    int total = ne * HK;
    int stride = gridDim.x * blockDim.x;
    for (int idx = blockIdx.x * blockDim.x + threadIdx.x; idx < total; idx += stride) {
        int e = idx / HK, k = idx - e * HK;
        int row = g_s2erow[e], col = g_s2ecol[e];
        float norm = rsqrtf(g_deg[row]) * g_s2ew[e] * rsqrtf(g_deg[col]);
        int s2 = g_slot2[row];
        int s1 = g_slot1[col];
        if (s2 >= 0 && s2 < MAX2 && s1 >= 0 && s1 < CAP1)
            atomicAdd(&g_x1acc[s1 * HK + k], g_xw1[s2 * HK + k] * norm);
    }
}

// fused: layer1 finalize (relu) + layer2 at node 0
__global__ void k_layer2(const float* __restrict__ b1,
                         const float* __restrict__ g2w, const float* __restrict__ g2b) {
    __shared__ float coef[1024];
    __shared__ float xagg[HK];
    int tid = threadIdx.x;
    int n1 = min(g_n1, CAP1);
    for (int idx = tid; idx < n1 * HK; idx += blockDim.x) {
        int s = idx / HK, k = idx - s * HK;
        int v = g_s1nodes[s];
        float self = g_xw1[g_slot2[v] * HK + k] / g_deg[v];
        g_x1[idx] = fmaxf(g_x1acc[idx] + self + b1[k], 0.f);
    }
    int n1c = min(n1, 1024);
    int ncnt = min(g_s1cnt, CAP1);
    for (int i = tid; i < n1c; i += blockDim.x) coef[i] = 0.f;
    __syncthreads();
    float d0 = rsqrtf(g_deg[0]);
    for (int i = tid; i < ncnt; i += blockDim.x) {
        int row = g_s1rows[i];
        float nrm = rsqrtf(g_deg[row]) * g_s1w[i] * d0;
        int s = g_slot1[row];
        if (s >= 0 && s < n1c) atomicAdd(&coef[s], nrm);
    }
    __syncthreads();
    if (tid == 0) coef[g_slot1[0]] += 1.0f / g_deg[0];
    __syncthreads();
    if (tid < HK) {
        float a = 0.f;
        for (int s = 0; s < n1c; s++) a += coef[s] * g_x1[s * HK + tid];
        xagg[tid] = a;
    }
    __syncthreads();
    if (tid < HK) {
        float a = g2b[tid];
        #pragma unroll
        for (int j = 0; j < HK; j++) a += xagg[j] * g2w[tid * HK + j];
        g_interact[tid] = a;
    }
}

// ---------------- decoder: 3-CTA cluster, Whh slice in registers ----------------
__device__ __forceinline__ unsigned smem_u32(const void* p) {
    return (unsigned)__cvta_generic_to_shared(p);
}
__device__ __forceinline__ void st_remote_f32(unsigned laddr, unsigned rank, float v) {
    unsigned r;
    asm volatile("mapa.shared::cluster.u32 %0, %1, %2;" : "=r"(r) : "r"(laddr), "r"(rank));
    asm volatile("st.shared::cluster.f32 [%0], %1;" :: "r"(r), "f"(v) : "memory");
}
__device__ __forceinline__ void cluster_sync_() {
    asm volatile("barrier.cluster.arrive.aligned;" ::: "memory");
    asm volatile("barrier.cluster.wait.aligned;" ::: "memory");
}
__device__ __forceinline__ unsigned ctarank_() {
    unsigned r; asm("mov.u32 %0, %%cluster_ctarank;" : "=r"(r)); return r;
}

__global__ __launch_bounds__(432, 1) __cluster_dims__(3, 1, 1)
void k_decoder(const float* __restrict__ past,
               const float* __restrict__ dbih, const float* __restrict__ dbhh,
               const float* __restrict__ fcw, const float* __restrict__ fcb,
               float* __restrict__ out) {
    __shared__ float sc[H3];          // state_conc (144-dim!)
    __shared__ float sga0[D3];        // step-0 gi (full, replicated across CTAs)
    __shared__ float sbih[D3], sbhh[D3];
    __shared__ float h[H3];
    __shared__ float part[432];
    __shared__ float gates[2][D3];    // double-buffered gh (full, replicated)
    __shared__ float pres[2];
    int tid = threadIdx.x;
    unsigned ct = ctarank_();
    int o = tid % H3, p = tid / H3;

    // register-resident Whh slice: rows [ct*144, ct*144+144), cols [48p, 48p+48)
    float w[48];
    {
        const float* wbase = g_wdecR + ((ct * 3 + p) * 48) * H3 + o;
        #pragma unroll
        for (int j = 0; j < 48; j++) w[j] = wbase[j * H3];
    }
    if (tid < HK) { sc[tid] = g_interact[tid]; sc[HK + tid] = g_target[tid]; sc[2 * HK + tid] = g_futv[tid]; }
    if (tid < D3) { sbih[tid] = dbih[tid]; sbhh[tid] = dbhh[tid]; }
    if (tid < H3) h[tid] = 0.f;
    if (tid < 2) pres[tid] = past[(TPAST - 1) * 2 + tid];
    __syncthreads();

    // step-0 gi: row gr = ct*144+o, partial over input dims j in [48p, 48p+48)
    {
        float a0 = 0.f, a1 = 0.f;
        int gr = ct * H3 + o;
        const float* wt = g_wihT + gr;
        int j0 = p * 48;
        #pragma unroll
        for (int j = j0; j < j0 + 48; j += 2) {
            a0 += wt[j * D3] * sc[j];
            a1 += wt[(j + 1) * D3] * sc[j + 1];
        }
        part[tid] = a0 + a1;
    }
    __syncthreads();
    if (tid < H3) {
        int gi = ct * H3 + tid;
        float v = part[tid] + part[tid + H3] + part[tid + 2 * H3] + sbih[gi];
        sga0[gi] = v;
        unsigned laddr = smem_u32(&sga0[gi]);
        st_remote_f32(laddr, (ct + 1) % 3, v);
        st_remote_f32(laddr, (ct + 2) % 3, v);
    }
    __syncthreads();

    for (int i = 0; i < TFUT; i++) {
        // gh slice matvec from registers
        {
            float a0 = 0.f, a1 = 0.f;
            const float* hp = &h[p * 48];
            #pragma unroll
            for (int j = 0; j < 48; j += 2) {
                a0 += w[j] * hp[j];
                a1 += w[j + 1] * hp[j + 1];
            }
            part[tid] = a0 + a1;
        }
        __syncthreads();
        int buf = i & 1;
        if (tid < H3) {
            int gi = ct * H3 + tid;
            float g = part[tid] + part[tid + H3] + part[tid + 2 * H3] + sbhh[gi];
            gates[buf][gi] = g;
            unsigned laddr = smem_u32(&gates[buf][gi]);
            st_remote_f32(laddr, (ct + 1) % 3, g);
            st_remote_f32(laddr, (ct + 2) % 3, g);
        }
        cluster_sync_();
        if (tid < H3) {
            float gar = i ? sbih[tid]          : sga0[tid];
            float gaz = i ? sbih[H3 + tid]     : sga0[H3 + tid];
            float gan = i ? sbih[2 * H3 + tid] : sga0[2 * H3 + tid];
            float r = sigmoidf(gar + gates[buf][tid]);
            float z = sigmoidf(gaz + gates[buf][H3 + tid]);
            float n = tanhf(gan + r * gates[buf][2 * H3 + tid]);
            h[tid] = (1.f - z) * n + z * h[tid];
        }
        __syncthreads();
        if (ct == 0 && tid < 64) {
            int d = tid >> 5, lane = tid & 31;
            float a = 0.f;
            for (int j = lane; j < H3; j += 32) a += h[j] * fcw[d * H3 + j];
            #pragma unroll
            for (int off = 16; off; off >>= 1) a += __shfl_down_sync(0xffffffffu, a, off);
            if (lane == 0) { pres[d] += a + fcb[d]; out[i * 2 + d] = pres[d]; }
        }
        __syncthreads();
    }
}

// ---------------- launch ----------------
extern "C" void kernel_launch(void* const* d_in, const int* in_sizes, int n_in,
                              void* d_out, int out_size) {
    (void)in_sizes; (void)n_in; (void)out_size;
    const float* past   = (const float*)d_in[0];
    const float* future = (const float*)d_in[1];
    const float* x      = (const float*)d_in[2];
    const int*   ei     = (const int*)  d_in[3];
    const float* ew     = (const float*)d_in[4];
    const float* cpw  = (const float*)d_in[5];
    const float* cpb  = (const float*)d_in[6];
    const float* cfw  = (const float*)d_in[7];
    const float* cfb  = (const float*)d_in[8];
    const float* pWih = (const float*)d_in[9];
    const float* pWhh = (const float*)d_in[10];
    const float* pbih = (const float*)d_in[11];
    const float* pbhh = (const float*)d_in[12];
    const float* fWih = (const float*)d_in[13];
    const float* fWhh = (const float*)d_in[14];
    const float* fbih = (const float*)d_in[15];
    const float* fbhh = (const float*)d_in[16];
    const float* dWih = (const float*)d_in[17];
    const float* dWhh = (const float*)d_in[18];
    const float* dbih = (const float*)d_in[19];
    const float* dbhh = (const float*)d_in[20];
    const float* fcw  = (const float*)d_in[21];
    const float* fcb  = (const float*)d_in[22];
    const float* g1w  = (const float*)d_in[23];
    const float* g1b  = (const float*)d_in[24];
    const float* g2w  = (const float*)d_in[25];
    const float* g2b  = (const float*)d_in[26];
    float* out = (float*)d_out;

    k_prep<<<1024, 256>>>(dWhh, dWih);
    k_passA<<<EE / 4 / 256, 256>>>(ei, ew);
    k_s1nodes<<<1, 256>>>();
    k_passB<<<EE / 4 / 256, 256>>>(ei, ew);
    k_gru_all<<<1026, 160>>>(x, past, future, cpw, cpb, cfw, cfb,
                             pWih, pWhh, pbih, pbhh, fWih, fWhh, fbih, fbhh, g1w);
    k_layer1<<<64, 256>>>();
    k_layer2<<<1, 256>>>(g1b, g2w, g2b);
    k_decoder<<<3, 432>>>(past, dbih, dbhh, fcw, fcb, out);
}